// round 14
// baseline (speedup 1.0000x reference)
#include <cuda_runtime.h>
#include <cuda_fp16.h>
#include <math_constants.h>

// LSS view transformer, GB300 sm_103a — balanced CSR gather v5.
// vs v4: lift rebuilt — single softmax (no d-split), feats staged in smem
// [cam][px][c], warp-per-pixel epilogue with STG.64 packed-fp16 stores
// (256B/warp wavefronts instead of 64B).
//
// k1 count : per-voxel entry counts + per-(voxel,d) exclusive offsets.
// k2 scan  : exclusive prefix sum over voxels (single block, shfl).
// k3 fill  : one thread per (d,pixel), closed-form rank (balanced).
// k4 lift  : 8-pixel tile; softmax once; T[d,p,c] fp16, full-width stores.
// k5 splat : 64-entry chunks per warp, 8 loads in flight, fp32 acc,
//            plain float4 stores interior / red.v4 at chunk boundaries.
// k6 transpose: g_acc (voxel-major) -> out (channel-major).

#define D_N   40
#define H_N   32
#define W_N   88
#define CAM_N 6
#define C_N   128
#define BEV   125
#define NPIX  (H_N * W_N)          // 2816
#define NVOX  (BEV * BEV)          // 15625
#define NENT  (D_N * NPIX)         // 112640
#define CHUNK 64
#define NWARP ((NENT + CHUNK - 1) / CHUNK)

__device__ __half g_T[(size_t)D_N * NPIX * C_N];  // ~28.9MB
__device__ float  g_acc[(size_t)NVOX * C_N];      // ~8MB (voxel, channel)
__device__ int    g_cnt[NVOX];
__device__ int    g_vstart[NVOX + 1];
__device__ int    g_dpre[D_N * NVOX];
__device__ int    g_entries[NENT];                // (d*NPIX+p)<<14 | v

// Exact fp32 op sequence of the reference (unfused; no FMA contraction).
__device__ __forceinline__ int ix_of(int w, float dv) {
    float xd = __fmul_rn((float)w, dv);
    float gx = __fadd_rn(__fmul_rn(__fdiv_rn(xd, 3567.0f), 100.0f), -50.0f);
    return (int)__fdiv_rn(__fadd_rn(gx, 50.0f), 0.8f);
}
__device__ __forceinline__ int iy_of(int h, float dv) {
    float yd = __fmul_rn((float)h, dv);
    float gy = __fadd_rn(__fmul_rn(__fdiv_rn(yd, 1271.0f), 100.0f), -50.0f);
    return (int)__fdiv_rn(__fadd_rn(gy, 50.0f), 0.8f);
}

__device__ __forceinline__ void build_runs(int* s_wp, int* s_hp, int tid) {
    for (int i = tid; i < D_N * BEV; i += 1024) { s_wp[i] = 0; s_hp[i] = 0; }
    __syncthreads();
    for (int i = tid; i < D_N * W_N; i += 1024) {
        int d = i / W_N, w = i - d * W_N;
        float dv = (float)(d + 2);
        int ix = ix_of(w, dv);
        if (ix < BEV && (w == 0 || ix_of(w - 1, dv) != ix)) {
            int e = w + 1;
            while (e < W_N && ix_of(e, dv) == ix) ++e;
            s_wp[d * BEV + ix] = w | (e << 8);
        }
    }
    for (int i = tid; i < D_N * H_N; i += 1024) {
        int d = i / H_N, h = i - d * H_N;
        float dv = (float)(d + 2);
        int iy = iy_of(h, dv);
        if (iy < BEV && (h == 0 || iy_of(h - 1, dv) != iy)) {
            int e = h + 1;
            while (e < H_N && iy_of(e, dv) == iy) ++e;
            s_hp[d * BEV + iy] = h | (e << 8);
        }
    }
    __syncthreads();
}

// ---- k1: counts + per-d offsets ------------------------------------------------
__global__ __launch_bounds__(1024) void count_kernel() {
    __shared__ int s_wp[D_N * BEV], s_hp[D_N * BEV];
    build_runs(s_wp, s_hp, threadIdx.x);
    const int v = blockIdx.x * 1024 + threadIdx.x;
    if (v >= NVOX) return;
    const int iy = v / BEV, ix = v - iy * BEV;
    int run = 0;
    #pragma unroll
    for (int d = 0; d < D_N; ++d) {
        int wp = s_wp[d * BEV + ix], hp = s_hp[d * BEV + iy];
        g_dpre[d * NVOX + v] = run;
        run += ((hp >> 8) - (hp & 255)) * ((wp >> 8) - (wp & 255));
    }
    g_cnt[v] = run;
}

// ---- k2: exclusive scan (shfl) ---------------------------------------------------
__global__ __launch_bounds__(1024) void scan_kernel() {
    __shared__ int s_ws[32];
    const int t = threadIdx.x, lane = t & 31, wid = t >> 5;
    int local[16], lsum = 0;
    #pragma unroll
    for (int j = 0; j < 16; ++j) {
        int v = t * 16 + j;
        int c = (v < NVOX) ? g_cnt[v] : 0;
        local[j] = lsum; lsum += c;
    }
    int x = lsum;
    #pragma unroll
    for (int off = 1; off < 32; off <<= 1) {
        int y = __shfl_up_sync(0xffffffffu, x, off);
        if (lane >= off) x += y;
    }
    if (lane == 31) s_ws[wid] = x;
    __syncthreads();
    if (wid == 0) {
        int y = s_ws[lane];
        #pragma unroll
        for (int off = 1; off < 32; off <<= 1) {
            int z = __shfl_up_sync(0xffffffffu, y, off);
            if (lane >= off) y += z;
        }
        s_ws[lane] = y;
    }
    __syncthreads();
    const int base = x - lsum + ((wid > 0) ? s_ws[wid - 1] : 0);
    #pragma unroll
    for (int j = 0; j < 16; ++j) {
        int v = t * 16 + j;
        if (v < NVOX) g_vstart[v] = base + local[j];
    }
    if (t == 1023) g_vstart[NVOX] = base + lsum;
}

// ---- k3: fill, one thread per (d,pixel) --------------------------------------------
__global__ __launch_bounds__(1024) void fill_kernel() {
    __shared__ int s_wp[D_N * BEV], s_hp[D_N * BEV];
    build_runs(s_wp, s_hp, threadIdx.x);
    const int idx = blockIdx.x * 1024 + threadIdx.x;
    if (idx >= NENT) return;
    const int d = idx / NPIX, p = idx - d * NPIX;
    const int h = p / W_N,   w = p - h * W_N;
    const float dv = (float)(d + 2);
    const int ix = ix_of(w, dv), iy = iy_of(h, dv);
    if (ix >= BEV || iy >= BEV) return;
    const int v  = iy * BEV + ix;
    const int wp = s_wp[d * BEV + ix], hp = s_hp[d * BEV + iy];
    const int wl = wp & 255, wh = wp >> 8, hl = hp & 255;
    const int rank = (h - hl) * (wh - wl) + (w - wl);
    const int pos  = g_vstart[v] + g_dpre[d * NVOX + v] + rank;
    g_entries[pos] = (idx << 14) | v;
}

// ---- k4: lift, 8-pixel tile, warp-per-pixel fp16 epilogue ---------------------------
__global__ __launch_bounds__(256) void lift_kernel(
    const float* __restrict__ img_feat,
    const float* __restrict__ depth_logits)
{
    __shared__ float s_l[CAM_N][D_N][8];             // probs (in place)
    __shared__ __align__(16) float s_f[CAM_N][8][C_N];  // [cam][px][c] 24KB

    const int h0  = (int)blockIdx.x / 11;
    const int w0  = ((int)blockIdx.x % 11) * 8;
    const int tid = threadIdx.x;

    // stage logits (6*40*8 floats, 32B-chunk coalesced)
    for (int i = tid; i < CAM_N * D_N * 8; i += 256) {
        int cam = i / (D_N * 8), r = i - cam * D_N * 8;
        int d = r >> 3, pl = r & 7;
        s_l[cam][d][pl] =
            depth_logits[((cam * D_N + d) * H_N + h0) * W_N + w0 + pl];
    }

    // stage feats transposed: thread=(c,q) loads float4 over w (sector-exact)
    {
        const int c = tid & 127, q = tid >> 7;
        const int FS = C_N * H_N * W_N;
        #pragma unroll
        for (int cam = 0; cam < CAM_N; ++cam) {
            float4 f = *reinterpret_cast<const float4*>(
                img_feat + cam * FS + (c * H_N + h0) * W_N + w0 + 4 * q);
            s_f[cam][4 * q + 0][c] = f.x;
            s_f[cam][4 * q + 1][c] = f.y;
            s_f[cam][4 * q + 2][c] = f.z;
            s_f[cam][4 * q + 3][c] = f.w;
        }
    }
    __syncthreads();

    // softmax: one thread per (cam, px), all passes serial in-thread
    if (tid < CAM_N * 8) {
        const int cam = tid >> 3, pp = tid & 7;
        float m = -CUDART_INF_F;
        #pragma unroll
        for (int d = 0; d < D_N; ++d) m = fmaxf(m, s_l[cam][d][pp]);
        float s = 0.0f;
        #pragma unroll
        for (int d = 0; d < D_N; ++d) {
            float e = __expf(s_l[cam][d][pp] - m);
            s_l[cam][d][pp] = e; s += e;
        }
        const float inv = 1.0f / s;
        #pragma unroll
        for (int d = 0; d < D_N; ++d) s_l[cam][d][pp] *= inv;
    }
    __syncthreads();

    // warp = pixel, lane = 4-channel group; 40 independent STG.64 per warp
    const int px   = tid >> 5;
    const int lane = tid & 31;
    const int c0   = lane * 4;
    const int p    = h0 * W_N + w0 + px;

    float4 fr[CAM_N];
    #pragma unroll
    for (int cam = 0; cam < CAM_N; ++cam)
        fr[cam] = *reinterpret_cast<const float4*>(&s_f[cam][px][c0]);

    #pragma unroll 4
    for (int d = 0; d < D_N; ++d) {
        float v0 = 0.f, v1 = 0.f, v2 = 0.f, v3 = 0.f;
        #pragma unroll
        for (int cam = 0; cam < CAM_N; ++cam) {
            const float pb = s_l[cam][d][px];
            v0 += pb * fr[cam].x; v1 += pb * fr[cam].y;
            v2 += pb * fr[cam].z; v3 += pb * fr[cam].w;
        }
        __half2 lo = __floats2half2_rn(v0, v1);
        __half2 hi = __floats2half2_rn(v2, v3);
        uint2 pk = make_uint2(*reinterpret_cast<unsigned*>(&lo),
                              *reinterpret_cast<unsigned*>(&hi));
        *reinterpret_cast<uint2*>(g_T + ((size_t)d * NPIX + p) * C_N + c0) = pk;
    }
}

// ---- k5: chunked segmented splat (fp16 loads, fp32 acc) -------------------------------
__global__ __launch_bounds__(256) void splat_kernel()
{
    const int gw   = ((int)blockIdx.x * 256 + (int)threadIdx.x) >> 5;
    const int lane = threadIdx.x & 31;
    const int total = g_vstart[NVOX];
    const int s0 = gw * CHUNK;
    if (s0 >= total) return;
    const int cnt = min(CHUNK, total - s0);
    const unsigned FULL = 0xffffffffu;

    const int prev_vox = (s0 > 0)           ? (g_entries[s0 - 1]   & 0x3FFF) : -1;
    const int next_vox = (s0 + cnt < total) ? (g_entries[s0 + cnt] & 0x3FFF) : -1;

    const int eA = g_entries[s0 + min(lane,      cnt - 1)];
    const int eB = g_entries[s0 + min(32 + lane, cnt - 1)];

    const uint2* __restrict__ T2 = reinterpret_cast<const uint2*>(g_T);

    float4 acc = make_float4(0.f, 0.f, 0.f, 0.f);
    int  cur   = __shfl_sync(FULL, eA, 0) & 0x3FFF;
    bool first = true;

    for (int base = 0; base < cnt; base += 8) {
        uint2 tb[8];
        int   vn[8];
        #pragma unroll
        for (int j = 0; j < 8; ++j) {
            int i = base + j;
            int e = __shfl_sync(FULL, (i < 32) ? eA : eB, i & 31);
            if (i < cnt)
                tb[j] = T2[(size_t)(e >> 14) * 32 + lane];
            int i1 = i + 1;
            int e1 = __shfl_sync(FULL, (i1 < 32) ? eA : eB, i1 & 31);
            vn[j]  = (i1 < cnt) ? (e1 & 0x3FFF) : -1;
        }
        #pragma unroll
        for (int j = 0; j < 8; ++j) {
            int i = base + j;
            if (i >= cnt) break;
            float2 lo = __half22float2(*reinterpret_cast<__half2*>(&tb[j].x));
            float2 hi = __half22float2(*reinterpret_cast<__half2*>(&tb[j].y));
            acc.x += lo.x; acc.y += lo.y; acc.z += hi.x; acc.w += hi.y;
            if (vn[j] != cur) {
                float* dst = g_acc + (size_t)cur * C_N + lane * 4;
                bool partial = (first && cur == prev_vox) ||
                               (i + 1 == cnt && cur == next_vox);
                if (partial) {
                    asm volatile("red.global.add.v4.f32 [%0], {%1,%2,%3,%4};"
                                 :: "l"(dst), "f"(acc.x), "f"(acc.y),
                                    "f"(acc.z), "f"(acc.w) : "memory");
                } else {
                    *reinterpret_cast<float4*>(dst) = acc;
                }
                acc   = make_float4(0.f, 0.f, 0.f, 0.f);
                first = false;
                cur   = vn[j];
            }
        }
    }
}

// ---- k6: transpose g_acc (voxel-major) -> out (channel-major) --------------------------
__global__ __launch_bounds__(256) void transpose_kernel(float* __restrict__ out)
{
    __shared__ float s[32][65];
    const int v0  = blockIdx.x * 32;
    const int z   = blockIdx.y;
    const int tid = threadIdx.x;

    const int rc = tid & 63;
    const int rv = tid >> 6;
    #pragma unroll
    for (int j = 0; j < 8; ++j) {
        int vl = rv + 4 * j;
        int v  = v0 + vl;
        s[vl][rc] = (v < NVOX) ? g_acc[(size_t)v * C_N + z * 64 + rc] : 0.0f;
    }
    __syncthreads();

    const int vl = tid & 31;
    const int cb = tid >> 5;
    const int v  = v0 + vl;
    if (v < NVOX) {
        #pragma unroll
        for (int c = 0; c < 8; ++c)
            out[(size_t)(z * 64 + cb + 8 * c) * NVOX + v] = s[vl][cb + 8 * c];
    }
}

extern "C" void kernel_launch(void* const* d_in, const int* in_sizes, int n_in,
                              void* d_out, int out_size)
{
    const float* img_feat     = (const float*)d_in[0];
    const float* depth_logits = (const float*)d_in[1];
    float* out = (float*)d_out;

    void* acc_ptr = nullptr;
    cudaGetSymbolAddress(&acc_ptr, g_acc);
    cudaMemsetAsync(acc_ptr, 0, (size_t)NVOX * C_N * sizeof(float), 0);

    count_kernel<<<(NVOX + 1023) / 1024, 1024>>>();
    scan_kernel<<<1, 1024>>>();
    fill_kernel<<<(NENT + 1023) / 1024, 1024>>>();
    lift_kernel<<<H_N * (W_N / 8), 256>>>(img_feat, depth_logits);
    splat_kernel<<<(NWARP * 32 + 255) / 256, 256>>>();
    transpose_kernel<<<dim3((NVOX + 31) / 32, 2), 256>>>(out);
}

// round 15
// speedup vs baseline: 1.6021x; 1.6021x over previous
#include <cuda_runtime.h>
#include <cuda_fp16.h>
#include <math_constants.h>

// LSS view transformer, GB300 sm_103a — balanced CSR gather v6.
// vs v5: splat CHUNK 64->32 (2x warps; splat is issue-bound, not byte-bound),
// memset removed (boundary voxels zeroed by tiny zeroseg kernel; transpose
// substitutes 0 for empty voxels).
//
// k1 count : per-voxel entry counts + per-(voxel,d) exclusive offsets.
// k2 scan  : exclusive prefix sum over voxels (single block, shfl).
// k3 fill  : one thread per (d,pixel), closed-form rank (balanced).
// k3b zeroseg: zero g_acc rows only for voxels whose CSR segment crosses a
//            chunk boundary (the only ones receiving REDs).
// k4 lift  : 8-pixel tile; softmax once; feats smem-transposed; warp-per-
//            pixel epilogue, STG.64 packed fp16 (256B/warp wavefronts).
// k5 splat : 32-entry chunks per warp, entries shfl-broadcast, 8 loads in
//            flight, fp32 acc; plain float4 store interior / red.v4 boundary.
// k6 transpose: g_acc (voxel-major) -> out (channel-major); cnt==0 -> 0.

#define D_N   40
#define H_N   32
#define W_N   88
#define CAM_N 6
#define C_N   128
#define BEV   125
#define NPIX  (H_N * W_N)          // 2816
#define NVOX  (BEV * BEV)          // 15625
#define NENT  (D_N * NPIX)         // 112640
#define CHUNK 32
#define NWARP ((NENT + CHUNK - 1) / CHUNK)   // 3520

__device__ __half g_T[(size_t)D_N * NPIX * C_N];  // ~28.9MB
__device__ float  g_acc[(size_t)NVOX * C_N];      // ~8MB (voxel, channel)
__device__ int    g_cnt[NVOX];
__device__ int    g_vstart[NVOX + 1];
__device__ int    g_dpre[D_N * NVOX];
__device__ int    g_entries[NENT];                // (d*NPIX+p)<<14 | v

// Exact fp32 op sequence of the reference (unfused; no FMA contraction).
__device__ __forceinline__ int ix_of(int w, float dv) {
    float xd = __fmul_rn((float)w, dv);
    float gx = __fadd_rn(__fmul_rn(__fdiv_rn(xd, 3567.0f), 100.0f), -50.0f);
    return (int)__fdiv_rn(__fadd_rn(gx, 50.0f), 0.8f);
}
__device__ __forceinline__ int iy_of(int h, float dv) {
    float yd = __fmul_rn((float)h, dv);
    float gy = __fadd_rn(__fmul_rn(__fdiv_rn(yd, 1271.0f), 100.0f), -50.0f);
    return (int)__fdiv_rn(__fadd_rn(gy, 50.0f), 0.8f);
}

__device__ __forceinline__ void build_runs(int* s_wp, int* s_hp, int tid) {
    for (int i = tid; i < D_N * BEV; i += 1024) { s_wp[i] = 0; s_hp[i] = 0; }
    __syncthreads();
    for (int i = tid; i < D_N * W_N; i += 1024) {
        int d = i / W_N, w = i - d * W_N;
        float dv = (float)(d + 2);
        int ix = ix_of(w, dv);
        if (ix < BEV && (w == 0 || ix_of(w - 1, dv) != ix)) {
            int e = w + 1;
            while (e < W_N && ix_of(e, dv) == ix) ++e;
            s_wp[d * BEV + ix] = w | (e << 8);
        }
    }
    for (int i = tid; i < D_N * H_N; i += 1024) {
        int d = i / H_N, h = i - d * H_N;
        float dv = (float)(d + 2);
        int iy = iy_of(h, dv);
        if (iy < BEV && (h == 0 || iy_of(h - 1, dv) != iy)) {
            int e = h + 1;
            while (e < H_N && iy_of(e, dv) == iy) ++e;
            s_hp[d * BEV + iy] = h | (e << 8);
        }
    }
    __syncthreads();
}

// ---- k1: counts + per-d offsets ------------------------------------------------
__global__ __launch_bounds__(1024) void count_kernel() {
    __shared__ int s_wp[D_N * BEV], s_hp[D_N * BEV];
    build_runs(s_wp, s_hp, threadIdx.x);
    const int v = blockIdx.x * 1024 + threadIdx.x;
    if (v >= NVOX) return;
    const int iy = v / BEV, ix = v - iy * BEV;
    int run = 0;
    #pragma unroll
    for (int d = 0; d < D_N; ++d) {
        int wp = s_wp[d * BEV + ix], hp = s_hp[d * BEV + iy];
        g_dpre[d * NVOX + v] = run;
        run += ((hp >> 8) - (hp & 255)) * ((wp >> 8) - (wp & 255));
    }
    g_cnt[v] = run;
}

// ---- k2: exclusive scan (shfl) ---------------------------------------------------
__global__ __launch_bounds__(1024) void scan_kernel() {
    __shared__ int s_ws[32];
    const int t = threadIdx.x, lane = t & 31, wid = t >> 5;
    int local[16], lsum = 0;
    #pragma unroll
    for (int j = 0; j < 16; ++j) {
        int v = t * 16 + j;
        int c = (v < NVOX) ? g_cnt[v] : 0;
        local[j] = lsum; lsum += c;
    }
    int x = lsum;
    #pragma unroll
    for (int off = 1; off < 32; off <<= 1) {
        int y = __shfl_up_sync(0xffffffffu, x, off);
        if (lane >= off) x += y;
    }
    if (lane == 31) s_ws[wid] = x;
    __syncthreads();
    if (wid == 0) {
        int y = s_ws[lane];
        #pragma unroll
        for (int off = 1; off < 32; off <<= 1) {
            int z = __shfl_up_sync(0xffffffffu, y, off);
            if (lane >= off) y += z;
        }
        s_ws[lane] = y;
    }
    __syncthreads();
    const int base = x - lsum + ((wid > 0) ? s_ws[wid - 1] : 0);
    #pragma unroll
    for (int j = 0; j < 16; ++j) {
        int v = t * 16 + j;
        if (v < NVOX) g_vstart[v] = base + local[j];
    }
    if (t == 1023) g_vstart[NVOX] = base + lsum;
}

// ---- k3: fill, one thread per (d,pixel) --------------------------------------------
__global__ __launch_bounds__(1024) void fill_kernel() {
    __shared__ int s_wp[D_N * BEV], s_hp[D_N * BEV];
    build_runs(s_wp, s_hp, threadIdx.x);
    const int idx = blockIdx.x * 1024 + threadIdx.x;
    if (idx >= NENT) return;
    const int d = idx / NPIX, p = idx - d * NPIX;
    const int h = p / W_N,   w = p - h * W_N;
    const float dv = (float)(d + 2);
    const int ix = ix_of(w, dv), iy = iy_of(h, dv);
    if (ix >= BEV || iy >= BEV) return;
    const int v  = iy * BEV + ix;
    const int wp = s_wp[d * BEV + ix], hp = s_hp[d * BEV + iy];
    const int wl = wp & 255, wh = wp >> 8, hl = hp & 255;
    const int rank = (h - hl) * (wh - wl) + (w - wl);
    const int pos  = g_vstart[v] + g_dpre[d * NVOX + v] + rank;
    g_entries[pos] = (idx << 14) | v;
}

// ---- k3b: zero g_acc only for chunk-boundary-crossing voxels ------------------------
__global__ __launch_bounds__(256) void zeroseg_kernel() {
    const int v = blockIdx.x * 256 + threadIdx.x;
    if (v >= NVOX) return;
    const int s = g_vstart[v], e = g_vstart[v + 1];
    if (s >= e) return;                          // empty voxel
    if ((s / CHUNK) == ((e - 1) / CHUNK)) return; // fully interior: plain store
    float4* dst = reinterpret_cast<float4*>(g_acc + (size_t)v * C_N);
    const float4 z = make_float4(0.f, 0.f, 0.f, 0.f);
    #pragma unroll
    for (int i = 0; i < C_N / 4; ++i) dst[i] = z;
}

// ---- k4: lift, 8-pixel tile, warp-per-pixel fp16 epilogue ---------------------------
__global__ __launch_bounds__(256) void lift_kernel(
    const float* __restrict__ img_feat,
    const float* __restrict__ depth_logits)
{
    __shared__ float s_l[CAM_N][D_N][8];
    __shared__ __align__(16) float s_f[CAM_N][8][C_N];

    const int h0  = (int)blockIdx.x / 11;
    const int w0  = ((int)blockIdx.x % 11) * 8;
    const int tid = threadIdx.x;

    for (int i = tid; i < CAM_N * D_N * 8; i += 256) {
        int cam = i / (D_N * 8), r = i - cam * D_N * 8;
        int d = r >> 3, pl = r & 7;
        s_l[cam][d][pl] =
            depth_logits[((cam * D_N + d) * H_N + h0) * W_N + w0 + pl];
    }
    {
        const int c = tid & 127, q = tid >> 7;
        const int FS = C_N * H_N * W_N;
        #pragma unroll
        for (int cam = 0; cam < CAM_N; ++cam) {
            float4 f = *reinterpret_cast<const float4*>(
                img_feat + cam * FS + (c * H_N + h0) * W_N + w0 + 4 * q);
            s_f[cam][4 * q + 0][c] = f.x;
            s_f[cam][4 * q + 1][c] = f.y;
            s_f[cam][4 * q + 2][c] = f.z;
            s_f[cam][4 * q + 3][c] = f.w;
        }
    }
    __syncthreads();

    if (tid < CAM_N * 8) {
        const int cam = tid >> 3, pp = tid & 7;
        float m = -CUDART_INF_F;
        #pragma unroll
        for (int d = 0; d < D_N; ++d) m = fmaxf(m, s_l[cam][d][pp]);
        float s = 0.0f;
        #pragma unroll
        for (int d = 0; d < D_N; ++d) {
            float e = __expf(s_l[cam][d][pp] - m);
            s_l[cam][d][pp] = e; s += e;
        }
        const float inv = 1.0f / s;
        #pragma unroll
        for (int d = 0; d < D_N; ++d) s_l[cam][d][pp] *= inv;
    }
    __syncthreads();

    const int px   = tid >> 5;
    const int lane = tid & 31;
    const int c0   = lane * 4;
    const int p    = h0 * W_N + w0 + px;

    float4 fr[CAM_N];
    #pragma unroll
    for (int cam = 0; cam < CAM_N; ++cam)
        fr[cam] = *reinterpret_cast<const float4*>(&s_f[cam][px][c0]);

    #pragma unroll 4
    for (int d = 0; d < D_N; ++d) {
        float v0 = 0.f, v1 = 0.f, v2 = 0.f, v3 = 0.f;
        #pragma unroll
        for (int cam = 0; cam < CAM_N; ++cam) {
            const float pb = s_l[cam][d][px];
            v0 += pb * fr[cam].x; v1 += pb * fr[cam].y;
            v2 += pb * fr[cam].z; v3 += pb * fr[cam].w;
        }
        __half2 lo = __floats2half2_rn(v0, v1);
        __half2 hi = __floats2half2_rn(v2, v3);
        uint2 pk = make_uint2(*reinterpret_cast<unsigned*>(&lo),
                              *reinterpret_cast<unsigned*>(&hi));
        *reinterpret_cast<uint2*>(g_T + ((size_t)d * NPIX + p) * C_N + c0) = pk;
    }
}

// ---- k5: 32-entry chunks per warp (fp16 loads, fp32 acc) ----------------------------
__global__ __launch_bounds__(256) void splat_kernel()
{
    const int gw   = ((int)blockIdx.x * 256 + (int)threadIdx.x) >> 5;
    const int lane = threadIdx.x & 31;
    const int total = g_vstart[NVOX];
    const int s0 = gw * CHUNK;
    if (s0 >= total) return;
    const int cnt = min(CHUNK, total - s0);
    const unsigned FULL = 0xffffffffu;

    const int prev_vox = (s0 > 0)           ? (g_entries[s0 - 1]   & 0x3FFF) : -1;
    const int next_vox = (s0 + cnt < total) ? (g_entries[s0 + cnt] & 0x3FFF) : -1;

    const int eA = g_entries[s0 + min(lane, cnt - 1)];   // one entry per lane

    const uint2* __restrict__ T2 = reinterpret_cast<const uint2*>(g_T);

    float4 acc = make_float4(0.f, 0.f, 0.f, 0.f);
    int  cur   = __shfl_sync(FULL, eA, 0) & 0x3FFF;
    bool first = true;

    for (int base = 0; base < cnt; base += 8) {
        uint2 tb[8];
        int   vn[8];
        #pragma unroll
        for (int j = 0; j < 8; ++j) {
            int i = base + j;
            int e = __shfl_sync(FULL, eA, i & 31);
            if (i < cnt)
                tb[j] = T2[(size_t)(e >> 14) * 32 + lane];
            int i1 = i + 1;
            int e1 = __shfl_sync(FULL, eA, i1 & 31);
            vn[j]  = (i1 < cnt) ? (e1 & 0x3FFF) : -1;
        }
        #pragma unroll
        for (int j = 0; j < 8; ++j) {
            int i = base + j;
            if (i >= cnt) break;
            float2 lo = __half22float2(*reinterpret_cast<__half2*>(&tb[j].x));
            float2 hi = __half22float2(*reinterpret_cast<__half2*>(&tb[j].y));
            acc.x += lo.x; acc.y += lo.y; acc.z += hi.x; acc.w += hi.y;
            if (vn[j] != cur) {
                float* dst = g_acc + (size_t)cur * C_N + lane * 4;
                bool partial = (first && cur == prev_vox) ||
                               (i + 1 == cnt && cur == next_vox);
                if (partial) {
                    asm volatile("red.global.add.v4.f32 [%0], {%1,%2,%3,%4};"
                                 :: "l"(dst), "f"(acc.x), "f"(acc.y),
                                    "f"(acc.z), "f"(acc.w) : "memory");
                } else {
                    *reinterpret_cast<float4*>(dst) = acc;
                }
                acc   = make_float4(0.f, 0.f, 0.f, 0.f);
                first = false;
                cur   = vn[j];
            }
        }
    }
}

// ---- k6: transpose g_acc (voxel-major) -> out (channel-major); empty -> 0 ------------
__global__ __launch_bounds__(256) void transpose_kernel(float* __restrict__ out)
{
    __shared__ float s[32][65];
    const int v0  = blockIdx.x * 32;
    const int z   = blockIdx.y;
    const int tid = threadIdx.x;

    const int rc = tid & 63;
    const int rv = tid >> 6;
    #pragma unroll
    for (int j = 0; j < 8; ++j) {
        int vl = rv + 4 * j;
        int v  = v0 + vl;
        bool live = (v < NVOX) && (g_vstart[v] < g_vstart[v + 1]);
        s[vl][rc] = live ? g_acc[(size_t)v * C_N + z * 64 + rc] : 0.0f;
    }
    __syncthreads();

    const int vl = tid & 31;
    const int cb = tid >> 5;
    const int v  = v0 + vl;
    if (v < NVOX) {
        #pragma unroll
        for (int c = 0; c < 8; ++c)
            out[(size_t)(z * 64 + cb + 8 * c) * NVOX + v] = s[vl][cb + 8 * c];
    }
}

extern "C" void kernel_launch(void* const* d_in, const int* in_sizes, int n_in,
                              void* d_out, int out_size)
{
    const float* img_feat     = (const float*)d_in[0];
    const float* depth_logits = (const float*)d_in[1];
    float* out = (float*)d_out;

    count_kernel<<<(NVOX + 1023) / 1024, 1024>>>();
    scan_kernel<<<1, 1024>>>();
    fill_kernel<<<(NENT + 1023) / 1024, 1024>>>();
    zeroseg_kernel<<<(NVOX + 255) / 256, 256>>>();
    lift_kernel<<<H_N * (W_N / 8), 256>>>(img_feat, depth_logits);
    splat_kernel<<<(NWARP * 32 + 255) / 256, 256>>>();
    transpose_kernel<<<dim3((NVOX + 31) / 32, 2), 256>>>(out);
}

// round 16
// speedup vs baseline: 1.6079x; 1.0037x over previous
#include <cuda_runtime.h>
#include <cuda_fp16.h>
#include <math_constants.h>

// LSS view transformer, GB300 sm_103a — balanced CSR gather v6.
// vs v5: splat CHUNK 64->32 (2x warps; splat is issue-bound, not byte-bound),
// memset removed (boundary voxels zeroed by tiny zeroseg kernel; transpose
// substitutes 0 for empty voxels).
//
// k1 count : per-voxel entry counts + per-(voxel,d) exclusive offsets.
// k2 scan  : exclusive prefix sum over voxels (single block, shfl).
// k3 fill  : one thread per (d,pixel), closed-form rank (balanced).
// k3b zeroseg: zero g_acc rows only for voxels whose CSR segment crosses a
//            chunk boundary (the only ones receiving REDs).
// k4 lift  : 8-pixel tile; softmax once; feats smem-transposed; warp-per-
//            pixel epilogue, STG.64 packed fp16 (256B/warp wavefronts).
// k5 splat : 32-entry chunks per warp, entries shfl-broadcast, 8 loads in
//            flight, fp32 acc; plain float4 store interior / red.v4 boundary.
// k6 transpose: g_acc (voxel-major) -> out (channel-major); cnt==0 -> 0.

#define D_N   40
#define H_N   32
#define W_N   88
#define CAM_N 6
#define C_N   128
#define BEV   125
#define NPIX  (H_N * W_N)          // 2816
#define NVOX  (BEV * BEV)          // 15625
#define NENT  (D_N * NPIX)         // 112640
#define CHUNK 32
#define NWARP ((NENT + CHUNK - 1) / CHUNK)   // 3520

__device__ __half g_T[(size_t)D_N * NPIX * C_N];  // ~28.9MB
__device__ float  g_acc[(size_t)NVOX * C_N];      // ~8MB (voxel, channel)
__device__ int    g_cnt[NVOX];
__device__ int    g_vstart[NVOX + 1];
__device__ int    g_dpre[D_N * NVOX];
__device__ int    g_entries[NENT];                // (d*NPIX+p)<<14 | v

// Exact fp32 op sequence of the reference (unfused; no FMA contraction).
__device__ __forceinline__ int ix_of(int w, float dv) {
    float xd = __fmul_rn((float)w, dv);
    float gx = __fadd_rn(__fmul_rn(__fdiv_rn(xd, 3567.0f), 100.0f), -50.0f);
    return (int)__fdiv_rn(__fadd_rn(gx, 50.0f), 0.8f);
}
__device__ __forceinline__ int iy_of(int h, float dv) {
    float yd = __fmul_rn((float)h, dv);
    float gy = __fadd_rn(__fmul_rn(__fdiv_rn(yd, 1271.0f), 100.0f), -50.0f);
    return (int)__fdiv_rn(__fadd_rn(gy, 50.0f), 0.8f);
}

__device__ __forceinline__ void build_runs(int* s_wp, int* s_hp, int tid) {
    for (int i = tid; i < D_N * BEV; i += 1024) { s_wp[i] = 0; s_hp[i] = 0; }
    __syncthreads();
    for (int i = tid; i < D_N * W_N; i += 1024) {
        int d = i / W_N, w = i - d * W_N;
        float dv = (float)(d + 2);
        int ix = ix_of(w, dv);
        if (ix < BEV && (w == 0 || ix_of(w - 1, dv) != ix)) {
            int e = w + 1;
            while (e < W_N && ix_of(e, dv) == ix) ++e;
            s_wp[d * BEV + ix] = w | (e << 8);
        }
    }
    for (int i = tid; i < D_N * H_N; i += 1024) {
        int d = i / H_N, h = i - d * H_N;
        float dv = (float)(d + 2);
        int iy = iy_of(h, dv);
        if (iy < BEV && (h == 0 || iy_of(h - 1, dv) != iy)) {
            int e = h + 1;
            while (e < H_N && iy_of(e, dv) == iy) ++e;
            s_hp[d * BEV + iy] = h | (e << 8);
        }
    }
    __syncthreads();
}

// ---- k1: counts + per-d offsets ------------------------------------------------
__global__ __launch_bounds__(1024) void count_kernel() {
    __shared__ int s_wp[D_N * BEV], s_hp[D_N * BEV];
    build_runs(s_wp, s_hp, threadIdx.x);
    const int v = blockIdx.x * 1024 + threadIdx.x;
    if (v >= NVOX) return;
    const int iy = v / BEV, ix = v - iy * BEV;
    int run = 0;
    #pragma unroll
    for (int d = 0; d < D_N; ++d) {
        int wp = s_wp[d * BEV + ix], hp = s_hp[d * BEV + iy];
        g_dpre[d * NVOX + v] = run;
        run += ((hp >> 8) - (hp & 255)) * ((wp >> 8) - (wp & 255));
    }
    g_cnt[v] = run;
}

// ---- k2: exclusive scan (shfl) ---------------------------------------------------
__global__ __launch_bounds__(1024) void scan_kernel() {
    __shared__ int s_ws[32];
    const int t = threadIdx.x, lane = t & 31, wid = t >> 5;
    int local[16], lsum = 0;
    #pragma unroll
    for (int j = 0; j < 16; ++j) {
        int v = t * 16 + j;
        int c = (v < NVOX) ? g_cnt[v] : 0;
        local[j] = lsum; lsum += c;
    }
    int x = lsum;
    #pragma unroll
    for (int off = 1; off < 32; off <<= 1) {
        int y = __shfl_up_sync(0xffffffffu, x, off);
        if (lane >= off) x += y;
    }
    if (lane == 31) s_ws[wid] = x;
    __syncthreads();
    if (wid == 0) {
        int y = s_ws[lane];
        #pragma unroll
        for (int off = 1; off < 32; off <<= 1) {
            int z = __shfl_up_sync(0xffffffffu, y, off);
            if (lane >= off) y += z;
        }
        s_ws[lane] = y;
    }
    __syncthreads();
    const int base = x - lsum + ((wid > 0) ? s_ws[wid - 1] : 0);
    #pragma unroll
    for (int j = 0; j < 16; ++j) {
        int v = t * 16 + j;
        if (v < NVOX) g_vstart[v] = base + local[j];
    }
    if (t == 1023) g_vstart[NVOX] = base + lsum;
}

// ---- k3: fill, one thread per (d,pixel) --------------------------------------------
__global__ __launch_bounds__(1024) void fill_kernel() {
    __shared__ int s_wp[D_N * BEV], s_hp[D_N * BEV];
    build_runs(s_wp, s_hp, threadIdx.x);
    const int idx = blockIdx.x * 1024 + threadIdx.x;
    if (idx >= NENT) return;
    const int d = idx / NPIX, p = idx - d * NPIX;
    const int h = p / W_N,   w = p - h * W_N;
    const float dv = (float)(d + 2);
    const int ix = ix_of(w, dv), iy = iy_of(h, dv);
    if (ix >= BEV || iy >= BEV) return;
    const int v  = iy * BEV + ix;
    const int wp = s_wp[d * BEV + ix], hp = s_hp[d * BEV + iy];
    const int wl = wp & 255, wh = wp >> 8, hl = hp & 255;
    const int rank = (h - hl) * (wh - wl) + (w - wl);
    const int pos  = g_vstart[v] + g_dpre[d * NVOX + v] + rank;
    g_entries[pos] = (idx << 14) | v;
}

// ---- k3b: zero g_acc only for chunk-boundary-crossing voxels ------------------------
__global__ __launch_bounds__(256) void zeroseg_kernel() {
    const int v = blockIdx.x * 256 + threadIdx.x;
    if (v >= NVOX) return;
    const int s = g_vstart[v], e = g_vstart[v + 1];
    if (s >= e) return;                          // empty voxel
    if ((s / CHUNK) == ((e - 1) / CHUNK)) return; // fully interior: plain store
    float4* dst = reinterpret_cast<float4*>(g_acc + (size_t)v * C_N);
    const float4 z = make_float4(0.f, 0.f, 0.f, 0.f);
    #pragma unroll
    for (int i = 0; i < C_N / 4; ++i) dst[i] = z;
}

// ---- k4: lift, 8-pixel tile, warp-per-pixel fp16 epilogue ---------------------------
__global__ __launch_bounds__(256) void lift_kernel(
    const float* __restrict__ img_feat,
    const float* __restrict__ depth_logits)
{
    __shared__ float s_l[CAM_N][D_N][8];
    __shared__ __align__(16) float s_f[CAM_N][8][C_N];

    const int h0  = (int)blockIdx.x / 11;
    const int w0  = ((int)blockIdx.x % 11) * 8;
    const int tid = threadIdx.x;

    for (int i = tid; i < CAM_N * D_N * 8; i += 256) {
        int cam = i / (D_N * 8), r = i - cam * D_N * 8;
        int d = r >> 3, pl = r & 7;
        s_l[cam][d][pl] =
            depth_logits[((cam * D_N + d) * H_N + h0) * W_N + w0 + pl];
    }
    {
        const int c = tid & 127, q = tid >> 7;
        const int FS = C_N * H_N * W_N;
        #pragma unroll
        for (int cam = 0; cam < CAM_N; ++cam) {
            float4 f = *reinterpret_cast<const float4*>(
                img_feat + cam * FS + (c * H_N + h0) * W_N + w0 + 4 * q);
            s_f[cam][4 * q + 0][c] = f.x;
            s_f[cam][4 * q + 1][c] = f.y;
            s_f[cam][4 * q + 2][c] = f.z;
            s_f[cam][4 * q + 3][c] = f.w;
        }
    }
    __syncthreads();

    if (tid < CAM_N * 8) {
        const int cam = tid >> 3, pp = tid & 7;
        float m = -CUDART_INF_F;
        #pragma unroll
        for (int d = 0; d < D_N; ++d) m = fmaxf(m, s_l[cam][d][pp]);
        float s = 0.0f;
        #pragma unroll
        for (int d = 0; d < D_N; ++d) {
            float e = __expf(s_l[cam][d][pp] - m);
            s_l[cam][d][pp] = e; s += e;
        }
        const float inv = 1.0f / s;
        #pragma unroll
        for (int d = 0; d < D_N; ++d) s_l[cam][d][pp] *= inv;
    }
    __syncthreads();

    const int px   = tid >> 5;
    const int lane = tid & 31;
    const int c0   = lane * 4;
    const int p    = h0 * W_N + w0 + px;

    float4 fr[CAM_N];
    #pragma unroll
    for (int cam = 0; cam < CAM_N; ++cam)
        fr[cam] = *reinterpret_cast<const float4*>(&s_f[cam][px][c0]);

    #pragma unroll 4
    for (int d = 0; d < D_N; ++d) {
        float v0 = 0.f, v1 = 0.f, v2 = 0.f, v3 = 0.f;
        #pragma unroll
        for (int cam = 0; cam < CAM_N; ++cam) {
            const float pb = s_l[cam][d][px];
            v0 += pb * fr[cam].x; v1 += pb * fr[cam].y;
            v2 += pb * fr[cam].z; v3 += pb * fr[cam].w;
        }
        __half2 lo = __floats2half2_rn(v0, v1);
        __half2 hi = __floats2half2_rn(v2, v3);
        uint2 pk = make_uint2(*reinterpret_cast<unsigned*>(&lo),
                              *reinterpret_cast<unsigned*>(&hi));
        *reinterpret_cast<uint2*>(g_T + ((size_t)d * NPIX + p) * C_N + c0) = pk;
    }
}

// ---- k5: 32-entry chunks per warp (fp16 loads, fp32 acc) ----------------------------
__global__ __launch_bounds__(256) void splat_kernel()
{
    const int gw   = ((int)blockIdx.x * 256 + (int)threadIdx.x) >> 5;
    const int lane = threadIdx.x & 31;
    const int total = g_vstart[NVOX];
    const int s0 = gw * CHUNK;
    if (s0 >= total) return;
    const int cnt = min(CHUNK, total - s0);
    const unsigned FULL = 0xffffffffu;

    const int prev_vox = (s0 > 0)           ? (g_entries[s0 - 1]   & 0x3FFF) : -1;
    const int next_vox = (s0 + cnt < total) ? (g_entries[s0 + cnt] & 0x3FFF) : -1;

    const int eA = g_entries[s0 + min(lane, cnt - 1)];   // one entry per lane

    const uint2* __restrict__ T2 = reinterpret_cast<const uint2*>(g_T);

    float4 acc = make_float4(0.f, 0.f, 0.f, 0.f);
    int  cur   = __shfl_sync(FULL, eA, 0) & 0x3FFF;
    bool first = true;

    for (int base = 0; base < cnt; base += 8) {
        uint2 tb[8];
        int   vn[8];
        #pragma unroll
        for (int j = 0; j < 8; ++j) {
            int i = base + j;
            int e = __shfl_sync(FULL, eA, i & 31);
            if (i < cnt)
                tb[j] = T2[(size_t)(e >> 14) * 32 + lane];
            int i1 = i + 1;
            int e1 = __shfl_sync(FULL, eA, i1 & 31);
            vn[j]  = (i1 < cnt) ? (e1 & 0x3FFF) : -1;
        }
        #pragma unroll
        for (int j = 0; j < 8; ++j) {
            int i = base + j;
            if (i >= cnt) break;
            float2 lo = __half22float2(*reinterpret_cast<__half2*>(&tb[j].x));
            float2 hi = __half22float2(*reinterpret_cast<__half2*>(&tb[j].y));
            acc.x += lo.x; acc.y += lo.y; acc.z += hi.x; acc.w += hi.y;
            if (vn[j] != cur) {
                float* dst = g_acc + (size_t)cur * C_N + lane * 4;
                bool partial = (first && cur == prev_vox) ||
                               (i + 1 == cnt && cur == next_vox);
                if (partial) {
                    asm volatile("red.global.add.v4.f32 [%0], {%1,%2,%3,%4};"
                                 :: "l"(dst), "f"(acc.x), "f"(acc.y),
                                    "f"(acc.z), "f"(acc.w) : "memory");
                } else {
                    *reinterpret_cast<float4*>(dst) = acc;
                }
                acc   = make_float4(0.f, 0.f, 0.f, 0.f);
                first = false;
                cur   = vn[j];
            }
        }
    }
}

// ---- k6: transpose g_acc (voxel-major) -> out (channel-major); empty -> 0 ------------
__global__ __launch_bounds__(256) void transpose_kernel(float* __restrict__ out)
{
    __shared__ float s[32][65];
    const int v0  = blockIdx.x * 32;
    const int z   = blockIdx.y;
    const int tid = threadIdx.x;

    const int rc = tid & 63;
    const int rv = tid >> 6;
    #pragma unroll
    for (int j = 0; j < 8; ++j) {
        int vl = rv + 4 * j;
        int v  = v0 + vl;
        bool live = (v < NVOX) && (g_vstart[v] < g_vstart[v + 1]);
        s[vl][rc] = live ? g_acc[(size_t)v * C_N + z * 64 + rc] : 0.0f;
    }
    __syncthreads();

    const int vl = tid & 31;
    const int cb = tid >> 5;
    const int v  = v0 + vl;
    if (v < NVOX) {
        #pragma unroll
        for (int c = 0; c < 8; ++c)
            out[(size_t)(z * 64 + cb + 8 * c) * NVOX + v] = s[vl][cb + 8 * c];
    }
}

extern "C" void kernel_launch(void* const* d_in, const int* in_sizes, int n_in,
                              void* d_out, int out_size)
{
    const float* img_feat     = (const float*)d_in[0];
    const float* depth_logits = (const float*)d_in[1];
    float* out = (float*)d_out;

    count_kernel<<<(NVOX + 1023) / 1024, 1024>>>();
    scan_kernel<<<1, 1024>>>();
    fill_kernel<<<(NENT + 1023) / 1024, 1024>>>();
    zeroseg_kernel<<<(NVOX + 255) / 256, 256>>>();
    lift_kernel<<<H_N * (W_N / 8), 256>>>(img_feat, depth_logits);
    splat_kernel<<<(NWARP * 32 + 255) / 256, 256>>>();
    transpose_kernel<<<dim3((NVOX + 31) / 32, 2), 256>>>(out);
}